// round 11
// baseline (speedup 1.0000x reference)
#include <cuda_runtime.h>
#include <cuda_bf16.h>
#include <cstdint>

#define BATCH 2
#define SEQ   2048
#define DIM   1024
#define NH    16
#define HD    64
#define MAXD  128
#define MTOT  (BATCH * SEQ)

typedef __nv_bfloat16 bf16;

// Scratch (static device allocations are allowed)
__device__ bf16 g_xh[MTOT * DIM];
__device__ bf16 g_xl[MTOT * DIM];
__device__ bf16 g_wh[4 * DIM * DIM];
__device__ bf16 g_wl[4 * DIM * DIM];
__device__ bf16 g_qh[MTOT * DIM];
__device__ bf16 g_ql[MTOT * DIM];
__device__ bf16 g_kh[MTOT * DIM];
__device__ bf16 g_kl[MTOT * DIM];
__device__ bf16 g_vh[MTOT * DIM];
__device__ bf16 g_vl[MTOT * DIM];
__device__ bf16 g_ath[MTOT * DIM];
__device__ bf16 g_atl[MTOT * DIM];

// ---------------------------------------------------------------------------
// helpers
// ---------------------------------------------------------------------------
__device__ __forceinline__ uint32_t smem_u32(const void* p) {
    uint32_t a;
    asm("{ .reg .u64 t; cvta.to.shared.u64 t, %1; cvt.u32.u64 %0, t; }" : "=r"(a) : "l"(p));
    return a;
}
__device__ __forceinline__ void ldsm4(uint32_t* r, uint32_t addr) {
    asm volatile("ldmatrix.sync.aligned.m8n8.x4.shared.b16 {%0,%1,%2,%3}, [%4];"
                 : "=r"(r[0]), "=r"(r[1]), "=r"(r[2]), "=r"(r[3]) : "r"(addr));
}
__device__ __forceinline__ void ldsm4t(uint32_t* r, uint32_t addr) {
    asm volatile("ldmatrix.sync.aligned.m8n8.x4.trans.shared.b16 {%0,%1,%2,%3}, [%4];"
                 : "=r"(r[0]), "=r"(r[1]), "=r"(r[2]), "=r"(r[3]) : "r"(addr));
}
__device__ __forceinline__ void mma_bf(float* d, const uint32_t* a, uint32_t b0, uint32_t b1) {
    asm volatile("mma.sync.aligned.m16n8k16.row.col.f32.bf16.bf16.f32 "
                 "{%0,%1,%2,%3}, {%4,%5,%6,%7}, {%8,%9}, {%0,%1,%2,%3};"
                 : "+f"(d[0]), "+f"(d[1]), "+f"(d[2]), "+f"(d[3])
                 : "r"(a[0]), "r"(a[1]), "r"(a[2]), "r"(a[3]), "r"(b0), "r"(b1));
}
__device__ __forceinline__ void cpa16(uint32_t dst, const void* src) {
    asm volatile("cp.async.cg.shared.global [%0], [%1], 16;" :: "r"(dst), "l"(src));
}
#define CPA_COMMIT() asm volatile("cp.async.commit_group;" ::: "memory")
#define CPA_WAIT(n)  asm volatile("cp.async.wait_group %0;" :: "n"(n) : "memory")

__device__ __forceinline__ uint32_t pack_bf2(bf16 a, bf16 b) {
    __nv_bfloat162 t(a, b);
    return *reinterpret_cast<uint32_t*>(&t);
}
__device__ __forceinline__ void split2(float2 v, uint32_t& hi, uint32_t& lo) {
    bf16 h0 = __float2bfloat16_rn(v.x);
    bf16 l0 = __float2bfloat16_rn(v.x - __bfloat162float(h0));
    bf16 h1 = __float2bfloat16_rn(v.y);
    bf16 l1 = __float2bfloat16_rn(v.y - __bfloat162float(h1));
    hi = pack_bf2(h0, h1);
    lo = pack_bf2(l0, l1);
}

// ---------------------------------------------------------------------------
// one-shot split of x + 4 weights -> bf16 hi/lo
// ---------------------------------------------------------------------------
__global__ __launch_bounds__(256)
void split_all_kernel(const float* __restrict__ x,
                      const float* __restrict__ Wq, const float* __restrict__ Wk,
                      const float* __restrict__ Wv, const float* __restrict__ Wo)
{
    const int bid = blockIdx.x;
    const float* in;
    bf16 *hi, *lo;
    int i;
    if (bid < 4096) {
        in = x; hi = g_xh; lo = g_xl;
        i = bid * 256 + threadIdx.x;
    } else {
        const int z  = (bid - 4096) >> 10;
        const int lb = (bid - 4096) & 1023;
        in = (z == 0) ? Wq : (z == 1) ? Wk : (z == 2) ? Wv : Wo;
        hi = g_wh + (size_t)z * DIM * DIM;
        lo = g_wl + (size_t)z * DIM * DIM;
        i = lb * 256 + threadIdx.x;
    }
    float4 v = ((const float4*)in)[i];
    uint32_t h0, l0, h1, l1;
    split2(make_float2(v.x, v.y), h0, l0);
    split2(make_float2(v.z, v.w), h1, l1);
    ((uint2*)hi)[i] = make_uint2(h0, h1);
    ((uint2*)lo)[i] = make_uint2(l0, l1);
}

// ---------------------------------------------------------------------------
// HMMA split-bf16 GEMM, 128x64 tile, BK=32, 2-stage cp.async pipeline.
// 8 warps (4M x 2N), warp computes 32x32.  LDT2=40 -> 80B rows (16B aligned).
// smem 60 KB, ~80 regs -> 3 CTAs/SM.
// ---------------------------------------------------------------------------
#define BM   128
#define BN   64
#define BK2  32
#define LDT2 40                       // row stride (bf16): 80 B, 16B-aligned + conflict-free
#define A_T  (BM * LDT2)              // 5120 bf16 per A tensor per stage
#define W_T  (BN * LDT2)              // 2560 bf16 per W tensor per stage
#define STG2 (2 * A_T + 2 * W_T)      // 15360 bf16 per stage
#define SMEM_GEMM (2 * STG2 * 2)      // 61440 bytes

template <int SCATTER>
__device__ __forceinline__ void gemm_mma_body(
    const bf16* __restrict__ Ah, const bf16* __restrict__ Al,
    const bf16* __restrict__ Wh, const bf16* __restrict__ Wl,
    const float* __restrict__ bias, float* __restrict__ C,
    bf16* __restrict__ Ch, bf16* __restrict__ Cl)
{
    extern __shared__ __align__(16) char smem_raw[];
    bf16* smem = (bf16*)smem_raw;

    const int tid  = threadIdx.x;
    const int lane = tid & 31;
    const int wid  = tid >> 5;
    const int wm   = wid & 3;          // m offset 32*wm
    const int wn   = wid >> 2;         // n offset 32*wn
    const int m0   = blockIdx.y * BM;
    const int n0   = blockIdx.x * BN;

    float d[2][4][4];
#pragma unroll
    for (int i = 0; i < 2; i++)
#pragma unroll
        for (int j = 0; j < 4; j++)
#pragma unroll
            for (int t = 0; t < 4; t++) d[i][j][t] = 0.0f;

    const int aRow = wm * 32 + (lane & 15);
    const int aK   = (lane >> 4) * 8;
    const int bRow = wn * 32 + (lane & 7) + ((lane >> 4) << 3);
    const int bK   = ((lane >> 3) & 1) * 8;

    const uint32_t sb = smem_u32(smem);

    auto issue_stage = [&](int c, int st) {
        const int k0 = c * BK2;
        const uint32_t ub = sb + (uint32_t)(st * STG2) * 2;
        // A: 512 16B-chunks per tensor (128 rows x 4), 2 per thread
#pragma unroll
        for (int i = 0; i < 2; i++) {
            const int f = tid + i * 256;
            const int r = f >> 2, s = (f & 3) * 8;
            const size_t go = (size_t)(m0 + r) * DIM + k0 + s;
            const uint32_t so = (uint32_t)(r * LDT2 + s) * 2;
            cpa16(ub + so, Ah + go);
            cpa16(ub + A_T * 2 + so, Al + go);
        }
        // W: 256 chunks per tensor (64 rows x 4), 1 per thread
        {
            const int r = tid >> 2, s = (tid & 3) * 8;
            const size_t go = (size_t)(n0 + r) * DIM + k0 + s;
            const uint32_t so = (uint32_t)(r * LDT2 + s) * 2;
            cpa16(ub + 2 * A_T * 2 + so, Wh + go);
            cpa16(ub + (2 * A_T + W_T) * 2 + so, Wl + go);
        }
        CPA_COMMIT();
    };

    issue_stage(0, 0);
    for (int c = 0; c < DIM / BK2; c++) {
        const int st = c & 1;
        if (c + 1 < DIM / BK2) { issue_stage(c + 1, st ^ 1); CPA_WAIT(1); }
        else                   { CPA_WAIT(0); }
        __syncthreads();

        const uint32_t ub  = sb + (uint32_t)(st * STG2) * 2;
        const uint32_t uAh = ub;
        const uint32_t uAl = ub + A_T * 2;
        const uint32_t uWh = ub + 2 * A_T * 2;
        const uint32_t uWl = ub + (2 * A_T + W_T) * 2;

#pragma unroll
        for (int ks = 0; ks < 2; ks++) {
            const int ko = aK + ks * 16;
            uint32_t ah0[4], ah1[4], al0[4], al1[4];
            ldsm4(ah0, uAh + ((aRow)      * LDT2 + ko) * 2);
            ldsm4(ah1, uAh + ((aRow + 16) * LDT2 + ko) * 2);
            ldsm4(al0, uAl + ((aRow)      * LDT2 + ko) * 2);
            ldsm4(al1, uAl + ((aRow + 16) * LDT2 + ko) * 2);
            const int kb = bK + ks * 16;
#pragma unroll
            for (int np = 0; np < 2; np++) {
                uint32_t bh[4], bl[4];
                const uint32_t ro = ((np * 16 + bRow) * LDT2 + kb) * 2;
                ldsm4(bh, uWh + ro);
                ldsm4(bl, uWl + ro);
                const int n2 = np * 2;
                mma_bf(d[0][n2],     ah0, bh[0], bh[1]);
                mma_bf(d[0][n2 + 1], ah0, bh[2], bh[3]);
                mma_bf(d[1][n2],     ah1, bh[0], bh[1]);
                mma_bf(d[1][n2 + 1], ah1, bh[2], bh[3]);
                mma_bf(d[0][n2],     al0, bh[0], bh[1]);
                mma_bf(d[0][n2 + 1], al0, bh[2], bh[3]);
                mma_bf(d[1][n2],     al1, bh[0], bh[1]);
                mma_bf(d[1][n2 + 1], al1, bh[2], bh[3]);
                mma_bf(d[0][n2],     ah0, bl[0], bl[1]);
                mma_bf(d[0][n2 + 1], ah0, bl[2], bl[3]);
                mma_bf(d[1][n2],     ah1, bl[0], bl[1]);
                mma_bf(d[1][n2 + 1], ah1, bl[2], bl[3]);
            }
        }
        __syncthreads();
    }

    const int bidx  = m0 / SEQ;
    const int srow0 = (m0 - bidx * SEQ) + wm * 32 + (lane >> 2);
    const int cloc  = wn * 32 + 2 * (lane & 3);   // within 64-col tile
    const int ccol  = n0 + cloc;
#pragma unroll
    for (int nt = 0; nt < 4; nt++) {
        const float2 bb = *(const float2*)(bias + ccol + nt * 8);
#pragma unroll
        for (int mi = 0; mi < 2; mi++) {
            const int sr = srow0 + mi * 16;
            float2 v0 = make_float2(d[mi][nt][0] + bb.x, d[mi][nt][1] + bb.y);
            float2 v1 = make_float2(d[mi][nt][2] + bb.x, d[mi][nt][3] + bb.y);
            if (SCATTER) {
                const int h   = n0 >> 6;              // BN=64-aligned -> one head
                const int dof = cloc + nt * 8;
                const size_t base = ((size_t)bidx * NH + h) * SEQ;
                uint32_t hi, lo;
                split2(v0, hi, lo);
                *(uint32_t*)&Ch[(base + sr) * HD + dof] = hi;
                *(uint32_t*)&Cl[(base + sr) * HD + dof] = lo;
                split2(v1, hi, lo);
                *(uint32_t*)&Ch[(base + sr + 8) * HD + dof] = hi;
                *(uint32_t*)&Cl[(base + sr + 8) * HD + dof] = lo;
            } else {
                const size_t mrow = (size_t)(m0 + wm * 32 + (lane >> 2) + mi * 16);
                *(float2*)&C[mrow       * DIM + ccol + nt * 8] = v0;
                *(float2*)&C[(mrow + 8) * DIM + ccol + nt * 8] = v1;
            }
        }
    }
}

__global__ __launch_bounds__(256)
void qkv_mma_kernel(const bf16* __restrict__ xh, const bf16* __restrict__ xl,
                    const bf16* __restrict__ wh, const bf16* __restrict__ wl,
                    const float* __restrict__ bq, const float* __restrict__ bk,
                    const float* __restrict__ bv)
{
    const int z = blockIdx.z;
    const bf16* Wh = wh + (size_t)z * DIM * DIM;
    const bf16* Wl = wl + (size_t)z * DIM * DIM;
    const float* bias = (z == 0) ? bq : (z == 1) ? bk : bv;
    bf16* Ch = (z == 0) ? g_qh : (z == 1) ? g_kh : g_vh;
    bf16* Cl = (z == 0) ? g_ql : (z == 1) ? g_kl : g_vl;
    gemm_mma_body<1>(xh, xl, Wh, Wl, bias, nullptr, Ch, Cl);
}

__global__ __launch_bounds__(256)
void out_mma_kernel(const bf16* __restrict__ ah, const bf16* __restrict__ al,
                    const bf16* __restrict__ wh, const bf16* __restrict__ wl,
                    const float* __restrict__ bias, float* __restrict__ C)
{
    gemm_mma_body<0>(ah, al, wh + (size_t)3 * DIM * DIM, wl + (size_t)3 * DIM * DIM,
                     bias, C, nullptr, nullptr);
}

// ---------------------------------------------------------------------------
// Register-resident FA2 attention (unchanged from R9).
// ---------------------------------------------------------------------------
#define ALDT 72
#define ATILE (64 * ALDT)
#define SMEM_ATTN (6 * ATILE * 2)

__global__ __launch_bounds__(128)
void attn_mma_kernel(const float* __restrict__ rel_emb)
{
    extern __shared__ __align__(16) char smem[];
    bf16* sQh = (bf16*)smem;
    bf16* sQl = sQh + ATILE;
    bf16* sKh = sQl + ATILE;
    bf16* sKl = sKh + ATILE;
    bf16* sVh = sKl + ATILE;
    bf16* sVl = sVh + ATILE;

    const int tid  = threadIdx.x;
    const int lane = tid & 31;
    const int w    = tid >> 5;
    const int qt = blockIdx.x, h = blockIdx.y, b = blockIdx.z;
    const size_t bhb = ((size_t)b * NH + h) * SEQ;

    const uint32_t uQh = smem_u32(sQh), uQl = smem_u32(sQl);
    const uint32_t uKh = smem_u32(sKh), uKl = smem_u32(sKl);
    const uint32_t uVh = smem_u32(sVh), uVl = smem_u32(sVl);

    {
        const bf16* Qhp = g_qh + (bhb + qt * 64) * HD;
        const bf16* Qlp = g_ql + (bhb + qt * 64) * HD;
#pragma unroll
        for (int i = 0; i < 4; i++) {
            const int f = tid + i * 128, r = f >> 3, s = (f & 7) * 8;
            *(uint4*)(sQh + r * ALDT + s) = *(const uint4*)(Qhp + r * HD + s);
            *(uint4*)(sQl + r * ALDT + s) = *(const uint4*)(Qlp + r * HD + s);
        }
    }

    {
        const bf16* Khp = g_kh + bhb * HD;
        const bf16* Klp = g_kl + bhb * HD;
#pragma unroll
        for (int i = 0; i < 4; i++) {
            const int f = tid + i * 128, r = f >> 3, s = (f & 7) * 8;
            cpa16(uKh + (r * ALDT + s) * 2, Khp + r * HD + s);
            cpa16(uKl + (r * ALDT + s) * 2, Klp + r * HD + s);
        }
        CPA_COMMIT();
    }
    __syncthreads();

    const int aRow = w * 16 + (lane & 15);
    const int aK   = ((lane >> 4) & 1) * 8;
    uint32_t qh[4][4], ql[4][4];
#pragma unroll
    for (int ks = 0; ks < 4; ks++) {
        ldsm4(qh[ks], uQh + (aRow * ALDT + ks * 16 + aK) * 2);
        ldsm4(ql[ks], uQl + (aRow * ALDT + ks * 16 + aK) * 2);
    }

    const int bRowL = (lane & 7) + ((lane >> 4) & 1) * 8;
    const int bKoff = ((lane >> 3) & 1) * 8;
    const int vRowL = (lane & 7) + ((lane >> 3) & 1) * 8;
    const int vColL = ((lane >> 4) & 1) * 8;

    const int r0  = lane >> 2;
    const int qiA = qt * 64 + w * 16 + r0;
    const int cq  = 2 * (lane & 3);

    float o[8][4];
#pragma unroll
    for (int nt = 0; nt < 8; nt++)
#pragma unroll
        for (int t = 0; t < 4; t++) o[nt][t] = 0.0f;

    float mA = -1e30f, mB = -1e30f, lA = 0.0f, lB = 0.0f;

    const float bclo = __ldg(rel_emb + 0 * NH + h);
    const float bchi = __ldg(rel_emb + 2 * MAXD * NH + h);

    const int NT = SEQ / 64;
    for (int kt = 0; kt < NT; kt++) {
        {
            const bf16* Vhp = g_vh + (bhb + kt * 64) * HD;
            const bf16* Vlp = g_vl + (bhb + kt * 64) * HD;
#pragma unroll
            for (int i = 0; i < 4; i++) {
                const int f = tid + i * 128, r = f >> 3, s = (f & 7) * 8;
                cpa16(uVh + (r * ALDT + s) * 2, Vhp + r * HD + s);
                cpa16(uVl + (r * ALDT + s) * 2, Vlp + r * HD + s);
            }
            CPA_COMMIT();
        }
        CPA_WAIT(1);
        __syncthreads();

        float sf[8][4];
#pragma unroll
        for (int nt = 0; nt < 8; nt++)
#pragma unroll
            for (int t = 0; t < 4; t++) sf[nt][t] = 0.0f;

#pragma unroll
        for (int ks = 0; ks < 4; ks++) {
            const int kb = ks * 16 + bKoff;
#pragma unroll
            for (int p = 0; p < 4; p++) {
                uint32_t kh[4], kl[4];
                const uint32_t ro = ((p * 16 + bRowL) * ALDT + kb) * 2;
                ldsm4(kh, uKh + ro);
                ldsm4(kl, uKl + ro);
                const int nt = p * 2;
                mma_bf(sf[nt],     qh[ks], kh[0], kh[1]);
                mma_bf(sf[nt + 1], qh[ks], kh[2], kh[3]);
                mma_bf(sf[nt],     ql[ks], kh[0], kh[1]);
                mma_bf(sf[nt + 1], ql[ks], kh[2], kh[3]);
                mma_bf(sf[nt],     qh[ks], kl[0], kl[1]);
                mma_bf(sf[nt + 1], qh[ks], kl[2], kl[3]);
            }
        }

        {
            const int dq = qt - kt;
            if (dq >= 3 || dq <= -3) {
                const float bc = (dq >= 3) ? bchi : bclo;
#pragma unroll
                for (int nt = 0; nt < 8; nt++)
#pragma unroll
                    for (int t = 0; t < 4; t++) sf[nt][t] = sf[nt][t] * 0.125f + bc;
            } else {
                const int colb = kt * 64 + cq;
#pragma unroll
                for (int nt = 0; nt < 8; nt++) {
#pragma unroll
                    for (int j = 0; j < 2; j++) {
                        const int col = colb + nt * 8 + j;
                        int dA = qiA - col;
                        dA = max(-MAXD, min(MAXD, dA));
                        int dB = qiA + 8 - col;
                        dB = max(-MAXD, min(MAXD, dB));
                        sf[nt][j]     = sf[nt][j]     * 0.125f + __ldg(rel_emb + (dA + MAXD) * NH + h);
                        sf[nt][2 + j] = sf[nt][2 + j] * 0.125f + __ldg(rel_emb + (dB + MAXD) * NH + h);
                    }
                }
            }

            float mxA = -1e30f, mxB = -1e30f;
#pragma unroll
            for (int nt = 0; nt < 8; nt++) {
                mxA = fmaxf(mxA, fmaxf(sf[nt][0], sf[nt][1]));
                mxB = fmaxf(mxB, fmaxf(sf[nt][2], sf[nt][3]));
            }
            mxA = fmaxf(mxA, __shfl_xor_sync(0xFFFFFFFFu, mxA, 1));
            mxA = fmaxf(mxA, __shfl_xor_sync(0xFFFFFFFFu, mxA, 2));
            mxB = fmaxf(mxB, __shfl_xor_sync(0xFFFFFFFFu, mxB, 1));
            mxB = fmaxf(mxB, __shfl_xor_sync(0xFFFFFFFFu, mxB, 2));

            const float mnA = fmaxf(mA, mxA);
            const float mnB = fmaxf(mB, mxB);
            const float facA = __expf(mA - mnA);
            const float facB = __expf(mB - mnB);
            mA = mnA; mB = mnB;

            float sumA = 0.0f, sumB = 0.0f;
#pragma unroll
            for (int nt = 0; nt < 8; nt++) {
                sf[nt][0] = __expf(sf[nt][0] - mnA);
                sf[nt][1] = __expf(sf[nt][1] - mnA);
                sf[nt][2] = __expf(sf[nt][2] - mnB);
                sf[nt][3] = __expf(sf[nt][3] - mnB);
                sumA += sf[nt][0] + sf[nt][1];
                sumB += sf[nt][2] + sf[nt][3];
            }
            sumA += __shfl_xor_sync(0xFFFFFFFFu, sumA, 1);
            sumA += __shfl_xor_sync(0xFFFFFFFFu, sumA, 2);
            sumB += __shfl_xor_sync(0xFFFFFFFFu, sumB, 1);
            sumB += __shfl_xor_sync(0xFFFFFFFFu, sumB, 2);
            lA = lA * facA + sumA;
            lB = lB * facB + sumB;

#pragma unroll
            for (int nt = 0; nt < 8; nt++) {
                o[nt][0] *= facA; o[nt][1] *= facA;
                o[nt][2] *= facB; o[nt][3] *= facB;
            }
        }

        uint32_t ph[4][4], pl[4][4];
#pragma unroll
        for (int t = 0; t < 4; t++) {
            split2(make_float2(sf[2 * t][0],     sf[2 * t][1]),     ph[t][0], pl[t][0]);
            split2(make_float2(sf[2 * t][2],     sf[2 * t][3]),     ph[t][1], pl[t][1]);
            split2(make_float2(sf[2 * t + 1][0], sf[2 * t + 1][1]), ph[t][2], pl[t][2]);
            split2(make_float2(sf[2 * t + 1][2], sf[2 * t + 1][3]), ph[t][3], pl[t][3]);
        }

        CPA_WAIT(0);
        __syncthreads();

        if (kt + 1 < NT) {
            const bf16* Khp = g_kh + (bhb + (kt + 1) * 64) * HD;
            const bf16* Klp = g_kl + (bhb + (kt + 1) * 64) * HD;
#pragma unroll
            for (int i = 0; i < 4; i++) {
                const int f = tid + i * 128, r = f >> 3, s = (f & 7) * 8;
                cpa16(uKh + (r * ALDT + s) * 2, Khp + r * HD + s);
                cpa16(uKl + (r * ALDT + s) * 2, Klp + r * HD + s);
            }
            CPA_COMMIT();
        }

#pragma unroll
        for (int t = 0; t < 4; t++) {
            const int kr = t * 16 + vRowL;
#pragma unroll
            for (int nd = 0; nd < 4; nd++) {
                uint32_t vh[4], vl[4];
                const uint32_t vo = (kr * ALDT + nd * 16 + vColL) * 2;
                ldsm4t(vh, uVh + vo);
                ldsm4t(vl, uVl + vo);
                const int ntd = nd * 2;
                mma_bf(o[ntd],     ph[t], vh[0], vh[1]);
                mma_bf(o[ntd + 1], ph[t], vh[2], vh[3]);
                mma_bf(o[ntd],     pl[t], vh[0], vh[1]);
                mma_bf(o[ntd + 1], pl[t], vh[2], vh[3]);
                mma_bf(o[ntd],     ph[t], vl[0], vl[1]);
                mma_bf(o[ntd + 1], ph[t], vl[2], vl[3]);
            }
        }
        __syncthreads();
    }

    {
        const float iA = 1.0f / lA, iB = 1.0f / lB;
        const int rowA = qt * 64 + w * 16 + r0;
#pragma unroll
        for (int nt = 0; nt < 8; nt++) {
            const int col = h * HD + nt * 8 + cq;
            const size_t a0 = ((size_t)b * SEQ + rowA)     * DIM + col;
            const size_t a1 = ((size_t)b * SEQ + rowA + 8) * DIM + col;
            uint32_t hi, lo;
            split2(make_float2(o[nt][0] * iA, o[nt][1] * iA), hi, lo);
            *(uint32_t*)(g_ath + a0) = hi;
            *(uint32_t*)(g_atl + a0) = lo;
            split2(make_float2(o[nt][2] * iB, o[nt][3] * iB), hi, lo);
            *(uint32_t*)(g_ath + a1) = hi;
            *(uint32_t*)(g_atl + a1) = lo;
        }
    }
}

// ---------------------------------------------------------------------------
extern "C" void kernel_launch(void* const* d_in, const int* in_sizes, int n_in,
                              void* d_out, int out_size)
{
    const float* x   = (const float*)d_in[0];
    const float* Wq  = (const float*)d_in[1];
    const float* bq  = (const float*)d_in[2];
    const float* Wk  = (const float*)d_in[3];
    const float* bk  = (const float*)d_in[4];
    const float* Wv  = (const float*)d_in[5];
    const float* bv  = (const float*)d_in[6];
    const float* Wo  = (const float*)d_in[7];
    const float* bo  = (const float*)d_in[8];
    const float* rel = (const float*)d_in[9];
    float* out = (float*)d_out;

    bf16 *xh, *xl, *wh, *wl, *ath, *atl;
    cudaGetSymbolAddress((void**)&xh,  g_xh);
    cudaGetSymbolAddress((void**)&xl,  g_xl);
    cudaGetSymbolAddress((void**)&wh,  g_wh);
    cudaGetSymbolAddress((void**)&wl,  g_wl);
    cudaGetSymbolAddress((void**)&ath, g_ath);
    cudaGetSymbolAddress((void**)&atl, g_atl);

    split_all_kernel<<<4096 + 4 * 1024, 256>>>(x, Wq, Wk, Wv, Wo);

    cudaFuncSetAttribute(qkv_mma_kernel, cudaFuncAttributeMaxDynamicSharedMemorySize, SMEM_GEMM);
    cudaFuncSetAttribute(out_mma_kernel, cudaFuncAttributeMaxDynamicSharedMemorySize, SMEM_GEMM);
    cudaFuncSetAttribute(attn_mma_kernel, cudaFuncAttributeMaxDynamicSharedMemorySize, SMEM_ATTN);

    dim3 gq(DIM / BN, MTOT / BM, 3);
    qkv_mma_kernel<<<gq, 256, SMEM_GEMM>>>(xh, xl, wh, wl, bq, bk, bv);

    dim3 ga(SEQ / 64, NH, BATCH);
    attn_mma_kernel<<<ga, 128, SMEM_ATTN>>>(rel);

    dim3 go(DIM / BN, MTOT / BM);
    out_mma_kernel<<<go, 256, SMEM_GEMM>>>(ath, atl, wh, wl, bo, out);
}

// round 12
// speedup vs baseline: 1.0382x; 1.0382x over previous
#include <cuda_runtime.h>
#include <cuda_bf16.h>
#include <cstdint>

#define BATCH 2
#define SEQ   2048
#define DIM   1024
#define NH    16
#define HD    64
#define MAXD  128
#define MTOT  (BATCH * SEQ)

typedef __nv_bfloat16 bf16;

// Scratch (static device allocations are allowed)
__device__ bf16 g_xh[MTOT * DIM];
__device__ bf16 g_xl[MTOT * DIM];
__device__ bf16 g_wh[4 * DIM * DIM];
__device__ bf16 g_wl[4 * DIM * DIM];
__device__ bf16 g_qh[MTOT * DIM];
__device__ bf16 g_ql[MTOT * DIM];
__device__ bf16 g_kh[MTOT * DIM];
__device__ bf16 g_kl[MTOT * DIM];
__device__ bf16 g_vh[MTOT * DIM];
__device__ bf16 g_vl[MTOT * DIM];
__device__ bf16 g_ath[MTOT * DIM];
__device__ bf16 g_atl[MTOT * DIM];

// ---------------------------------------------------------------------------
// helpers
// ---------------------------------------------------------------------------
__device__ __forceinline__ uint32_t smem_u32(const void* p) {
    uint32_t a;
    asm("{ .reg .u64 t; cvta.to.shared.u64 t, %1; cvt.u32.u64 %0, t; }" : "=r"(a) : "l"(p));
    return a;
}
__device__ __forceinline__ void ldsm4(uint32_t* r, uint32_t addr) {
    asm volatile("ldmatrix.sync.aligned.m8n8.x4.shared.b16 {%0,%1,%2,%3}, [%4];"
                 : "=r"(r[0]), "=r"(r[1]), "=r"(r[2]), "=r"(r[3]) : "r"(addr));
}
__device__ __forceinline__ void ldsm4t(uint32_t* r, uint32_t addr) {
    asm volatile("ldmatrix.sync.aligned.m8n8.x4.trans.shared.b16 {%0,%1,%2,%3}, [%4];"
                 : "=r"(r[0]), "=r"(r[1]), "=r"(r[2]), "=r"(r[3]) : "r"(addr));
}
__device__ __forceinline__ void mma_bf(float* d, const uint32_t* a, uint32_t b0, uint32_t b1) {
    asm volatile("mma.sync.aligned.m16n8k16.row.col.f32.bf16.bf16.f32 "
                 "{%0,%1,%2,%3}, {%4,%5,%6,%7}, {%8,%9}, {%0,%1,%2,%3};"
                 : "+f"(d[0]), "+f"(d[1]), "+f"(d[2]), "+f"(d[3])
                 : "r"(a[0]), "r"(a[1]), "r"(a[2]), "r"(a[3]), "r"(b0), "r"(b1));
}
__device__ __forceinline__ void cpa16(uint32_t dst, const void* src) {
    asm volatile("cp.async.cg.shared.global [%0], [%1], 16;" :: "r"(dst), "l"(src));
}
#define CPA_COMMIT() asm volatile("cp.async.commit_group;" ::: "memory")
#define CPA_WAIT(n)  asm volatile("cp.async.wait_group %0;" :: "n"(n) : "memory")

__device__ __forceinline__ uint32_t pack_bf2(bf16 a, bf16 b) {
    __nv_bfloat162 t(a, b);
    return *reinterpret_cast<uint32_t*>(&t);
}
__device__ __forceinline__ void split2(float2 v, uint32_t& hi, uint32_t& lo) {
    bf16 h0 = __float2bfloat16_rn(v.x);
    bf16 l0 = __float2bfloat16_rn(v.x - __bfloat162float(h0));
    bf16 h1 = __float2bfloat16_rn(v.y);
    bf16 l1 = __float2bfloat16_rn(v.y - __bfloat162float(h1));
    hi = pack_bf2(h0, h1);
    lo = pack_bf2(l0, l1);
}

// ---------------------------------------------------------------------------
// one-shot split of x + 4 weights -> bf16 hi/lo
// ---------------------------------------------------------------------------
__global__ __launch_bounds__(256)
void split_all_kernel(const float* __restrict__ x,
                      const float* __restrict__ Wq, const float* __restrict__ Wk,
                      const float* __restrict__ Wv, const float* __restrict__ Wo)
{
    const int bid = blockIdx.x;
    const float* in;
    bf16 *hi, *lo;
    int i;
    if (bid < 4096) {
        in = x; hi = g_xh; lo = g_xl;
        i = bid * 256 + threadIdx.x;
    } else {
        const int z  = (bid - 4096) >> 10;
        const int lb = (bid - 4096) & 1023;
        in = (z == 0) ? Wq : (z == 1) ? Wk : (z == 2) ? Wv : Wo;
        hi = g_wh + (size_t)z * DIM * DIM;
        lo = g_wl + (size_t)z * DIM * DIM;
        i = lb * 256 + threadIdx.x;
    }
    float4 v = ((const float4*)in)[i];
    uint32_t h0, l0, h1, l1;
    split2(make_float2(v.x, v.y), h0, l0);
    split2(make_float2(v.z, v.w), h1, l1);
    ((uint2*)hi)[i] = make_uint2(h0, h1);
    ((uint2*)lo)[i] = make_uint2(l0, l1);
}

// ---------------------------------------------------------------------------
// HMMA split-bf16 GEMM: 256x128 CTA tile, 64x64 warp tile, BK=32, 2-stage
// cp.async pipeline. 8 warps (4M x 2N). 32 independent accum chains/warp,
// MMA:ldsm = 6:1. 1 CTA/SM (regs ~190, smem 120 KB).
// ---------------------------------------------------------------------------
#define BM   256
#define BN   128
#define BK2  32
#define LDT2 40                        // row stride (bf16) = 80 B, 16B-aligned
#define A_T  (BM * LDT2)               // 10240 bf16 per A tensor per stage
#define W_T  (BN * LDT2)               // 5120 bf16 per W tensor per stage
#define STG2 (2 * A_T + 2 * W_T)       // 30720 bf16 per stage
#define SMEM_GEMM (2 * STG2 * 2)       // 122880 bytes

template <int SCATTER>
__device__ __forceinline__ void gemm_mma_body(
    const bf16* __restrict__ Ah, const bf16* __restrict__ Al,
    const bf16* __restrict__ Wh, const bf16* __restrict__ Wl,
    const float* __restrict__ bias, float* __restrict__ C,
    bf16* __restrict__ Ch, bf16* __restrict__ Cl)
{
    extern __shared__ __align__(16) char smem_raw[];
    bf16* smem = (bf16*)smem_raw;

    const int tid  = threadIdx.x;
    const int lane = tid & 31;
    const int wid  = tid >> 5;
    const int wm   = wid & 3;          // m offset 64*wm
    const int wn   = wid >> 2;         // n offset 64*wn
    const int m0   = blockIdx.y * BM;
    const int n0   = blockIdx.x * BN;

    float d[4][8][4];                  // 128 accumulators: 4 m-tiles x 8 n-tiles
#pragma unroll
    for (int i = 0; i < 4; i++)
#pragma unroll
        for (int j = 0; j < 8; j++)
#pragma unroll
            for (int t = 0; t < 4; t++) d[i][j][t] = 0.0f;

    const int aRow = wm * 64 + (lane & 15);
    const int aK   = (lane >> 4) * 8;
    const int bRow = wn * 64 + (lane & 7) + ((lane >> 4) << 3);
    const int bK   = ((lane >> 3) & 1) * 8;

    const uint32_t sb = smem_u32(smem);

    auto issue_stage = [&](int c, int st) {
        const int k0 = c * BK2;
        const uint32_t ub = sb + (uint32_t)(st * STG2) * 2;
        // A: 1024 16B-chunks per tensor (256 rows x 4), 4 per thread
#pragma unroll
        for (int i = 0; i < 4; i++) {
            const int f = tid + i * 256;
            const int r = f >> 2, s = (f & 3) * 8;
            const size_t go = (size_t)(m0 + r) * DIM + k0 + s;
            const uint32_t so = (uint32_t)(r * LDT2 + s) * 2;
            cpa16(ub + so, Ah + go);
            cpa16(ub + A_T * 2 + so, Al + go);
        }
        // W: 512 chunks per tensor (128 rows x 4), 2 per thread
#pragma unroll
        for (int i = 0; i < 2; i++) {
            const int f = tid + i * 256;
            const int r = f >> 2, s = (f & 3) * 8;
            const size_t go = (size_t)(n0 + r) * DIM + k0 + s;
            const uint32_t so = (uint32_t)(r * LDT2 + s) * 2;
            cpa16(ub + 2 * A_T * 2 + so, Wh + go);
            cpa16(ub + (2 * A_T + W_T) * 2 + so, Wl + go);
        }
        CPA_COMMIT();
    };

    issue_stage(0, 0);
    for (int c = 0; c < DIM / BK2; c++) {
        const int st = c & 1;
        if (c + 1 < DIM / BK2) { issue_stage(c + 1, st ^ 1); CPA_WAIT(1); }
        else                   { CPA_WAIT(0); }
        __syncthreads();

        const uint32_t ub  = sb + (uint32_t)(st * STG2) * 2;
        const uint32_t uAh = ub;
        const uint32_t uAl = ub + A_T * 2;
        const uint32_t uWh = ub + 2 * A_T * 2;
        const uint32_t uWl = ub + (2 * A_T + W_T) * 2;

#pragma unroll
        for (int ks = 0; ks < 2; ks++) {
            const int ko = aK + ks * 16;
            uint32_t ah[4][4], al[4][4];
#pragma unroll
            for (int mi = 0; mi < 4; mi++) {
                ldsm4(ah[mi], uAh + ((aRow + mi * 16) * LDT2 + ko) * 2);
                ldsm4(al[mi], uAl + ((aRow + mi * 16) * LDT2 + ko) * 2);
            }
            const int kb = bK + ks * 16;
#pragma unroll
            for (int np = 0; np < 4; np++) {
                uint32_t bh[4], bl[4];
                const uint32_t ro = ((np * 16 + bRow) * LDT2 + kb) * 2;
                ldsm4(bh, uWh + ro);
                ldsm4(bl, uWl + ro);
                const int n2 = np * 2;
#pragma unroll
                for (int mi = 0; mi < 4; mi++) {
                    mma_bf(d[mi][n2],     ah[mi], bh[0], bh[1]);
                    mma_bf(d[mi][n2 + 1], ah[mi], bh[2], bh[3]);
                    mma_bf(d[mi][n2],     al[mi], bh[0], bh[1]);
                    mma_bf(d[mi][n2 + 1], al[mi], bh[2], bh[3]);
                    mma_bf(d[mi][n2],     ah[mi], bl[0], bl[1]);
                    mma_bf(d[mi][n2 + 1], ah[mi], bl[2], bl[3]);
                }
            }
        }
        __syncthreads();
    }

    const int bidx  = m0 / SEQ;                    // BM=256 divides SEQ -> one batch
    const int cbase = n0 + wn * 64;                // 64-aligned -> single head
    const int cq    = 2 * (lane & 3);
#pragma unroll
    for (int mi = 0; mi < 4; mi++) {
        const int srow0 = (m0 - bidx * SEQ) + wm * 64 + mi * 16 + (lane >> 2);
#pragma unroll
        for (int nt = 0; nt < 8; nt++) {
            const float2 bb = *(const float2*)(bias + cbase + nt * 8 + cq);
            float2 v0 = make_float2(d[mi][nt][0] + bb.x, d[mi][nt][1] + bb.y);
            float2 v1 = make_float2(d[mi][nt][2] + bb.x, d[mi][nt][3] + bb.y);
            if (SCATTER) {
                const int h   = cbase >> 6;
                const int dof = nt * 8 + cq;
                const size_t base = ((size_t)bidx * NH + h) * SEQ;
                uint32_t hi, lo;
                split2(v0, hi, lo);
                *(uint32_t*)&Ch[(base + srow0) * HD + dof] = hi;
                *(uint32_t*)&Cl[(base + srow0) * HD + dof] = lo;
                split2(v1, hi, lo);
                *(uint32_t*)&Ch[(base + srow0 + 8) * HD + dof] = hi;
                *(uint32_t*)&Cl[(base + srow0 + 8) * HD + dof] = lo;
            } else {
                const size_t mrow = (size_t)(m0 + wm * 64 + mi * 16 + (lane >> 2));
                *(float2*)&C[mrow       * DIM + cbase + nt * 8 + cq] = v0;
                *(float2*)&C[(mrow + 8) * DIM + cbase + nt * 8 + cq] = v1;
            }
        }
    }
}

__global__ __launch_bounds__(256, 1)
void qkv_mma_kernel(const bf16* __restrict__ xh, const bf16* __restrict__ xl,
                    const bf16* __restrict__ wh, const bf16* __restrict__ wl,
                    const float* __restrict__ bq, const float* __restrict__ bk,
                    const float* __restrict__ bv)
{
    const int z = blockIdx.z;
    const bf16* Wh = wh + (size_t)z * DIM * DIM;
    const bf16* Wl = wl + (size_t)z * DIM * DIM;
    const float* bias = (z == 0) ? bq : (z == 1) ? bk : bv;
    bf16* Ch = (z == 0) ? g_qh : (z == 1) ? g_kh : g_vh;
    bf16* Cl = (z == 0) ? g_ql : (z == 1) ? g_kl : g_vl;
    gemm_mma_body<1>(xh, xl, Wh, Wl, bias, nullptr, Ch, Cl);
}

__global__ __launch_bounds__(256, 1)
void out_mma_kernel(const bf16* __restrict__ ah, const bf16* __restrict__ al,
                    const bf16* __restrict__ wh, const bf16* __restrict__ wl,
                    const float* __restrict__ bias, float* __restrict__ C)
{
    gemm_mma_body<0>(ah, al, wh + (size_t)3 * DIM * DIM, wl + (size_t)3 * DIM * DIM,
                     bias, C, nullptr, nullptr);
}

// ---------------------------------------------------------------------------
// Register-resident FA2 attention (unchanged from R9, the 635-us baseline).
// ---------------------------------------------------------------------------
#define ALDT 72
#define ATILE (64 * ALDT)
#define SMEM_ATTN (6 * ATILE * 2)

__global__ __launch_bounds__(128)
void attn_mma_kernel(const float* __restrict__ rel_emb)
{
    extern __shared__ __align__(16) char smem[];
    bf16* sQh = (bf16*)smem;
    bf16* sQl = sQh + ATILE;
    bf16* sKh = sQl + ATILE;
    bf16* sKl = sKh + ATILE;
    bf16* sVh = sKl + ATILE;
    bf16* sVl = sVh + ATILE;

    const int tid  = threadIdx.x;
    const int lane = tid & 31;
    const int w    = tid >> 5;
    const int qt = blockIdx.x, h = blockIdx.y, b = blockIdx.z;
    const size_t bhb = ((size_t)b * NH + h) * SEQ;

    const uint32_t uQh = smem_u32(sQh), uQl = smem_u32(sQl);
    const uint32_t uKh = smem_u32(sKh), uKl = smem_u32(sKl);
    const uint32_t uVh = smem_u32(sVh), uVl = smem_u32(sVl);

    {
        const bf16* Qhp = g_qh + (bhb + qt * 64) * HD;
        const bf16* Qlp = g_ql + (bhb + qt * 64) * HD;
#pragma unroll
        for (int i = 0; i < 4; i++) {
            const int f = tid + i * 128, r = f >> 3, s = (f & 7) * 8;
            *(uint4*)(sQh + r * ALDT + s) = *(const uint4*)(Qhp + r * HD + s);
            *(uint4*)(sQl + r * ALDT + s) = *(const uint4*)(Qlp + r * HD + s);
        }
    }

    {
        const bf16* Khp = g_kh + bhb * HD;
        const bf16* Klp = g_kl + bhb * HD;
#pragma unroll
        for (int i = 0; i < 4; i++) {
            const int f = tid + i * 128, r = f >> 3, s = (f & 7) * 8;
            cpa16(uKh + (r * ALDT + s) * 2, Khp + r * HD + s);
            cpa16(uKl + (r * ALDT + s) * 2, Klp + r * HD + s);
        }
        CPA_COMMIT();
    }
    __syncthreads();

    const int aRow = w * 16 + (lane & 15);
    const int aK   = ((lane >> 4) & 1) * 8;
    uint32_t qh[4][4], ql[4][4];
#pragma unroll
    for (int ks = 0; ks < 4; ks++) {
        ldsm4(qh[ks], uQh + (aRow * ALDT + ks * 16 + aK) * 2);
        ldsm4(ql[ks], uQl + (aRow * ALDT + ks * 16 + aK) * 2);
    }

    const int bRowL = (lane & 7) + ((lane >> 4) & 1) * 8;
    const int bKoff = ((lane >> 3) & 1) * 8;
    const int vRowL = (lane & 7) + ((lane >> 3) & 1) * 8;
    const int vColL = ((lane >> 4) & 1) * 8;

    const int r0  = lane >> 2;
    const int qiA = qt * 64 + w * 16 + r0;
    const int cq  = 2 * (lane & 3);

    float o[8][4];
#pragma unroll
    for (int nt = 0; nt < 8; nt++)
#pragma unroll
        for (int t = 0; t < 4; t++) o[nt][t] = 0.0f;

    float mA = -1e30f, mB = -1e30f, lA = 0.0f, lB = 0.0f;

    const float bclo = __ldg(rel_emb + 0 * NH + h);
    const float bchi = __ldg(rel_emb + 2 * MAXD * NH + h);

    const int NT = SEQ / 64;
    for (int kt = 0; kt < NT; kt++) {
        {
            const bf16* Vhp = g_vh + (bhb + kt * 64) * HD;
            const bf16* Vlp = g_vl + (bhb + kt * 64) * HD;
#pragma unroll
            for (int i = 0; i < 4; i++) {
                const int f = tid + i * 128, r = f >> 3, s = (f & 7) * 8;
                cpa16(uVh + (r * ALDT + s) * 2, Vhp + r * HD + s);
                cpa16(uVl + (r * ALDT + s) * 2, Vlp + r * HD + s);
            }
            CPA_COMMIT();
        }
        CPA_WAIT(1);
        __syncthreads();

        float sf[8][4];
#pragma unroll
        for (int nt = 0; nt < 8; nt++)
#pragma unroll
            for (int t = 0; t < 4; t++) sf[nt][t] = 0.0f;

#pragma unroll
        for (int ks = 0; ks < 4; ks++) {
            const int kb = ks * 16 + bKoff;
#pragma unroll
            for (int p = 0; p < 4; p++) {
                uint32_t kh[4], kl[4];
                const uint32_t ro = ((p * 16 + bRowL) * ALDT + kb) * 2;
                ldsm4(kh, uKh + ro);
                ldsm4(kl, uKl + ro);
                const int nt = p * 2;
                mma_bf(sf[nt],     qh[ks], kh[0], kh[1]);
                mma_bf(sf[nt + 1], qh[ks], kh[2], kh[3]);
                mma_bf(sf[nt],     ql[ks], kh[0], kh[1]);
                mma_bf(sf[nt + 1], ql[ks], kh[2], kh[3]);
                mma_bf(sf[nt],     qh[ks], kl[0], kl[1]);
                mma_bf(sf[nt + 1], qh[ks], kl[2], kl[3]);
            }
        }

        {
            const int dq = qt - kt;
            if (dq >= 3 || dq <= -3) {
                const float bc = (dq >= 3) ? bchi : bclo;
#pragma unroll
                for (int nt = 0; nt < 8; nt++)
#pragma unroll
                    for (int t = 0; t < 4; t++) sf[nt][t] = sf[nt][t] * 0.125f + bc;
            } else {
                const int colb = kt * 64 + cq;
#pragma unroll
                for (int nt = 0; nt < 8; nt++) {
#pragma unroll
                    for (int j = 0; j < 2; j++) {
                        const int col = colb + nt * 8 + j;
                        int dA = qiA - col;
                        dA = max(-MAXD, min(MAXD, dA));
                        int dB = qiA + 8 - col;
                        dB = max(-MAXD, min(MAXD, dB));
                        sf[nt][j]     = sf[nt][j]     * 0.125f + __ldg(rel_emb + (dA + MAXD) * NH + h);
                        sf[nt][2 + j] = sf[nt][2 + j] * 0.125f + __ldg(rel_emb + (dB + MAXD) * NH + h);
                    }
                }
            }

            float mxA = -1e30f, mxB = -1e30f;
#pragma unroll
            for (int nt = 0; nt < 8; nt++) {
                mxA = fmaxf(mxA, fmaxf(sf[nt][0], sf[nt][1]));
                mxB = fmaxf(mxB, fmaxf(sf[nt][2], sf[nt][3]));
            }
            mxA = fmaxf(mxA, __shfl_xor_sync(0xFFFFFFFFu, mxA, 1));
            mxA = fmaxf(mxA, __shfl_xor_sync(0xFFFFFFFFu, mxA, 2));
            mxB = fmaxf(mxB, __shfl_xor_sync(0xFFFFFFFFu, mxB, 1));
            mxB = fmaxf(mxB, __shfl_xor_sync(0xFFFFFFFFu, mxB, 2));

            const float mnA = fmaxf(mA, mxA);
            const float mnB = fmaxf(mB, mxB);
            const float facA = __expf(mA - mnA);
            const float facB = __expf(mB - mnB);
            mA = mnA; mB = mnB;

            float sumA = 0.0f, sumB = 0.0f;
#pragma unroll
            for (int nt = 0; nt < 8; nt++) {
                sf[nt][0] = __expf(sf[nt][0] - mnA);
                sf[nt][1] = __expf(sf[nt][1] - mnA);
                sf[nt][2] = __expf(sf[nt][2] - mnB);
                sf[nt][3] = __expf(sf[nt][3] - mnB);
                sumA += sf[nt][0] + sf[nt][1];
                sumB += sf[nt][2] + sf[nt][3];
            }
            sumA += __shfl_xor_sync(0xFFFFFFFFu, sumA, 1);
            sumA += __shfl_xor_sync(0xFFFFFFFFu, sumA, 2);
            sumB += __shfl_xor_sync(0xFFFFFFFFu, sumB, 1);
            sumB += __shfl_xor_sync(0xFFFFFFFFu, sumB, 2);
            lA = lA * facA + sumA;
            lB = lB * facB + sumB;

#pragma unroll
            for (int nt = 0; nt < 8; nt++) {
                o[nt][0] *= facA; o[nt][1] *= facA;
                o[nt][2] *= facB; o[nt][3] *= facB;
            }
        }

        uint32_t ph[4][4], pl[4][4];
#pragma unroll
        for (int t = 0; t < 4; t++) {
            split2(make_float2(sf[2 * t][0],     sf[2 * t][1]),     ph[t][0], pl[t][0]);
            split2(make_float2(sf[2 * t][2],     sf[2 * t][3]),     ph[t][1], pl[t][1]);
            split2(make_float2(sf[2 * t + 1][0], sf[2 * t + 1][1]), ph[t][2], pl[t][2]);
            split2(make_float2(sf[2 * t + 1][2], sf[2 * t + 1][3]), ph[t][3], pl[t][3]);
        }

        CPA_WAIT(0);
        __syncthreads();

        if (kt + 1 < NT) {
            const bf16* Khp = g_kh + (bhb + (kt + 1) * 64) * HD;
            const bf16* Klp = g_kl + (bhb + (kt + 1) * 64) * HD;
#pragma unroll
            for (int i = 0; i < 4; i++) {
                const int f = tid + i * 128, r = f >> 3, s = (f & 7) * 8;
                cpa16(uKh + (r * ALDT + s) * 2, Khp + r * HD + s);
                cpa16(uKl + (r * ALDT + s) * 2, Klp + r * HD + s);
            }
            CPA_COMMIT();
        }

#pragma unroll
        for (int t = 0; t < 4; t++) {
            const int kr = t * 16 + vRowL;
#pragma unroll
            for (int nd = 0; nd < 4; nd++) {
                uint32_t vh[4], vl[4];
                const uint32_t vo = (kr * ALDT + nd * 16 + vColL) * 2;
                ldsm4t(vh, uVh + vo);
                ldsm4t(vl, uVl + vo);
                const int ntd = nd * 2;
                mma_bf(o[ntd],     ph[t], vh[0], vh[1]);
                mma_bf(o[ntd + 1], ph[t], vh[2], vh[3]);
                mma_bf(o[ntd],     pl[t], vh[0], vh[1]);
                mma_bf(o[ntd + 1], pl[t], vh[2], vh[3]);
                mma_bf(o[ntd],     ph[t], vl[0], vl[1]);
                mma_bf(o[ntd + 1], ph[t], vl[2], vl[3]);
            }
        }
        __syncthreads();
    }

    {
        const float iA = 1.0f / lA, iB = 1.0f / lB;
        const int rowA = qt * 64 + w * 16 + r0;
#pragma unroll
        for (int nt = 0; nt < 8; nt++) {
            const int col = h * HD + nt * 8 + cq;
            const size_t a0 = ((size_t)b * SEQ + rowA)     * DIM + col;
            const size_t a1 = ((size_t)b * SEQ + rowA + 8) * DIM + col;
            uint32_t hi, lo;
            split2(make_float2(o[nt][0] * iA, o[nt][1] * iA), hi, lo);
            *(uint32_t*)(g_ath + a0) = hi;
            *(uint32_t*)(g_atl + a0) = lo;
            split2(make_float2(o[nt][2] * iB, o[nt][3] * iB), hi, lo);
            *(uint32_t*)(g_ath + a1) = hi;
            *(uint32_t*)(g_atl + a1) = lo;
        }
    }
}

// ---------------------------------------------------------------------------
extern "C" void kernel_launch(void* const* d_in, const int* in_sizes, int n_in,
                              void* d_out, int out_size)
{
    const float* x   = (const float*)d_in[0];
    const float* Wq  = (const float*)d_in[1];
    const float* bq  = (const float*)d_in[2];
    const float* Wk  = (const float*)d_in[3];
    const float* bk  = (const float*)d_in[4];
    const float* Wv  = (const float*)d_in[5];
    const float* bv  = (const float*)d_in[6];
    const float* Wo  = (const float*)d_in[7];
    const float* bo  = (const float*)d_in[8];
    const float* rel = (const float*)d_in[9];
    float* out = (float*)d_out;

    bf16 *xh, *xl, *wh, *wl, *ath, *atl;
    cudaGetSymbolAddress((void**)&xh,  g_xh);
    cudaGetSymbolAddress((void**)&xl,  g_xl);
    cudaGetSymbolAddress((void**)&wh,  g_wh);
    cudaGetSymbolAddress((void**)&wl,  g_wl);
    cudaGetSymbolAddress((void**)&ath, g_ath);
    cudaGetSymbolAddress((void**)&atl, g_atl);

    split_all_kernel<<<4096 + 4 * 1024, 256>>>(x, Wq, Wk, Wv, Wo);

    cudaFuncSetAttribute(qkv_mma_kernel, cudaFuncAttributeMaxDynamicSharedMemorySize, SMEM_GEMM);
    cudaFuncSetAttribute(out_mma_kernel, cudaFuncAttributeMaxDynamicSharedMemorySize, SMEM_GEMM);
    cudaFuncSetAttribute(attn_mma_kernel, cudaFuncAttributeMaxDynamicSharedMemorySize, SMEM_ATTN);

    dim3 gq(DIM / BN, MTOT / BM, 3);
    qkv_mma_kernel<<<gq, 256, SMEM_GEMM>>>(xh, xl, wh, wl, bq, bk, bv);

    dim3 ga(SEQ / 64, NH, BATCH);
    attn_mma_kernel<<<ga, 128, SMEM_ATTN>>>(rel);

    dim3 go(DIM / BN, MTOT / BM);
    out_mma_kernel<<<go, 256, SMEM_GEMM>>>(ath, atl, wh, wl, bo, out);
}

// round 14
// speedup vs baseline: 1.4375x; 1.3845x over previous
#include <cuda_runtime.h>
#include <cuda_fp16.h>
#include <cstdint>

#define BATCH 2
#define SEQ   2048
#define DIM   1024
#define NH    16
#define HD    64
#define MAXD  128
#define MTOT  (BATCH * SEQ)

typedef __half hlf;

// Scratch (static device allocations are allowed)
__device__ hlf g_xh[MTOT * DIM];
__device__ hlf g_xl[MTOT * DIM];
__device__ hlf g_wh[4 * DIM * DIM];
__device__ hlf g_qh[MTOT * DIM];
__device__ hlf g_ql[MTOT * DIM];
__device__ hlf g_kh[MTOT * DIM];
__device__ hlf g_vh[MTOT * DIM];
__device__ hlf g_ath[MTOT * DIM];
__device__ hlf g_atl[MTOT * DIM];

// ---------------------------------------------------------------------------
// helpers
// ---------------------------------------------------------------------------
__device__ __forceinline__ uint32_t smem_u32(const void* p) {
    uint32_t a;
    asm("{ .reg .u64 t; cvta.to.shared.u64 t, %1; cvt.u32.u64 %0, t; }" : "=r"(a) : "l"(p));
    return a;
}
__device__ __forceinline__ void ldsm4(uint32_t* r, uint32_t addr) {
    asm volatile("ldmatrix.sync.aligned.m8n8.x4.shared.b16 {%0,%1,%2,%3}, [%4];"
                 : "=r"(r[0]), "=r"(r[1]), "=r"(r[2]), "=r"(r[3]) : "r"(addr));
}
__device__ __forceinline__ void ldsm4t(uint32_t* r, uint32_t addr) {
    asm volatile("ldmatrix.sync.aligned.m8n8.x4.trans.shared.b16 {%0,%1,%2,%3}, [%4];"
                 : "=r"(r[0]), "=r"(r[1]), "=r"(r[2]), "=r"(r[3]) : "r"(addr));
}
__device__ __forceinline__ void mma_h(float* d, const uint32_t* a, uint32_t b0, uint32_t b1) {
    asm volatile("mma.sync.aligned.m16n8k16.row.col.f32.f16.f16.f32 "
                 "{%0,%1,%2,%3}, {%4,%5,%6,%7}, {%8,%9}, {%0,%1,%2,%3};"
                 : "+f"(d[0]), "+f"(d[1]), "+f"(d[2]), "+f"(d[3])
                 : "r"(a[0]), "r"(a[1]), "r"(a[2]), "r"(a[3]), "r"(b0), "r"(b1));
}
__device__ __forceinline__ void cpa16(uint32_t dst, const void* src) {
    asm volatile("cp.async.cg.shared.global [%0], [%1], 16;" :: "r"(dst), "l"(src));
}
#define CPA_COMMIT() asm volatile("cp.async.commit_group;" ::: "memory")
#define CPA_WAIT(n)  asm volatile("cp.async.wait_group %0;" :: "n"(n) : "memory")

__device__ __forceinline__ uint32_t pack_h2(hlf a, hlf b) {
    __half2 t = __halves2half2(a, b);
    return *reinterpret_cast<uint32_t*>(&t);
}
__device__ __forceinline__ void split2(float2 v, uint32_t& hi, uint32_t& lo) {
    hlf h0 = __float2half_rn(v.x);
    hlf l0 = __float2half_rn(v.x - __half2float(h0));
    hlf h1 = __float2half_rn(v.y);
    hlf l1 = __float2half_rn(v.y - __half2float(h1));
    hi = pack_h2(h0, h1);
    lo = pack_h2(l0, l1);
}
__device__ __forceinline__ uint32_t round_h2(float2 v) {
    return pack_h2(__float2half_rn(v.x), __float2half_rn(v.y));
}

// ---------------------------------------------------------------------------
// one-shot split: x -> fp16 hi/lo;  weights -> fp16 hi only
// ---------------------------------------------------------------------------
__global__ __launch_bounds__(256)
void split_all_kernel(const float* __restrict__ x,
                      const float* __restrict__ Wq, const float* __restrict__ Wk,
                      const float* __restrict__ Wv, const float* __restrict__ Wo)
{
    const int bid = blockIdx.x;
    if (bid < 4096) {                      // x: hi + lo
        const int i = bid * 256 + threadIdx.x;
        float4 v = ((const float4*)x)[i];
        uint32_t h0, l0, h1, l1;
        split2(make_float2(v.x, v.y), h0, l0);
        split2(make_float2(v.z, v.w), h1, l1);
        ((uint2*)g_xh)[i] = make_uint2(h0, h1);
        ((uint2*)g_xl)[i] = make_uint2(l0, l1);
    } else {                               // weights: hi only
        const int z  = (bid - 4096) >> 10;
        const int lb = (bid - 4096) & 1023;
        const float* in = (z == 0) ? Wq : (z == 1) ? Wk : (z == 2) ? Wv : Wo;
        hlf* hi = g_wh + (size_t)z * DIM * DIM;
        const int i = lb * 256 + threadIdx.x;
        float4 v = ((const float4*)in)[i];
        ((uint2*)hi)[i] = make_uint2(round_h2(make_float2(v.x, v.y)),
                                     round_h2(make_float2(v.z, v.w)));
    }
}

// ---------------------------------------------------------------------------
// HMMA 2-term fp16 GEMM: C = (Ah+Al) @ Wh^T + bias.
// 256x128 CTA tile, 64x64 warp tile, BK=32, 2-stage cp.async pipeline.
// ---------------------------------------------------------------------------
#define BM   256
#define BN   128
#define BK2  32
#define LDT2 40                        // row stride (halves) = 80 B, 16B-aligned
#define A_T  (BM * LDT2)               // 10240 per A tensor per stage
#define W_T  (BN * LDT2)               // 5120 per stage
#define STG2 (2 * A_T + W_T)           // 25600 halves per stage
#define SMEM_GEMM (2 * STG2 * 2)       // 102400 bytes

template <int SCATTER>
__device__ __forceinline__ void gemm_mma_body(
    const hlf* __restrict__ Ah, const hlf* __restrict__ Al,
    const hlf* __restrict__ Wh,
    const float* __restrict__ bias, float* __restrict__ C,
    hlf* __restrict__ Ch, hlf* __restrict__ Cl)
{
    extern __shared__ __align__(16) char smem_raw[];
    hlf* smem = (hlf*)smem_raw;

    const int tid  = threadIdx.x;
    const int lane = tid & 31;
    const int wid  = tid >> 5;
    const int wm   = wid & 3;
    const int wn   = wid >> 2;
    const int m0   = blockIdx.y * BM;
    const int n0   = blockIdx.x * BN;

    float d[4][8][4];
#pragma unroll
    for (int i = 0; i < 4; i++)
#pragma unroll
        for (int j = 0; j < 8; j++)
#pragma unroll
            for (int t = 0; t < 4; t++) d[i][j][t] = 0.0f;

    const int aRow = wm * 64 + (lane & 15);
    const int aK   = (lane >> 4) * 8;
    const int bRow = wn * 64 + (lane & 7) + ((lane >> 4) << 3);
    const int bK   = ((lane >> 3) & 1) * 8;

    const uint32_t sb = smem_u32(smem);

    auto issue_stage = [&](int c, int st) {
        const int k0 = c * BK2;
        const uint32_t ub = sb + (uint32_t)(st * STG2) * 2;
#pragma unroll
        for (int i = 0; i < 4; i++) {
            const int f = tid + i * 256;
            const int r = f >> 2, s = (f & 3) * 8;
            const size_t go = (size_t)(m0 + r) * DIM + k0 + s;
            const uint32_t so = (uint32_t)(r * LDT2 + s) * 2;
            cpa16(ub + so, Ah + go);
            cpa16(ub + A_T * 2 + so, Al + go);
        }
#pragma unroll
        for (int i = 0; i < 2; i++) {
            const int f = tid + i * 256;
            const int r = f >> 2, s = (f & 3) * 8;
            const size_t go = (size_t)(n0 + r) * DIM + k0 + s;
            const uint32_t so = (uint32_t)(r * LDT2 + s) * 2;
            cpa16(ub + 2 * A_T * 2 + so, Wh + go);
        }
        CPA_COMMIT();
    };

    issue_stage(0, 0);
    for (int c = 0; c < DIM / BK2; c++) {
        const int st = c & 1;
        if (c + 1 < DIM / BK2) { issue_stage(c + 1, st ^ 1); CPA_WAIT(1); }
        else                   { CPA_WAIT(0); }
        __syncthreads();

        const uint32_t ub  = sb + (uint32_t)(st * STG2) * 2;
        const uint32_t uAh = ub;
        const uint32_t uAl = ub + A_T * 2;
        const uint32_t uWh = ub + 2 * A_T * 2;

#pragma unroll
        for (int ks = 0; ks < 2; ks++) {
            const int ko = aK + ks * 16;
            uint32_t ah[4][4], al[4][4];
#pragma unroll
            for (int mi = 0; mi < 4; mi++) {
                ldsm4(ah[mi], uAh + ((aRow + mi * 16) * LDT2 + ko) * 2);
                ldsm4(al[mi], uAl + ((aRow + mi * 16) * LDT2 + ko) * 2);
            }
            const int kb = bK + ks * 16;
#pragma unroll
            for (int np = 0; np < 4; np++) {
                uint32_t bh[4];
                ldsm4(bh, uWh + ((np * 16 + bRow) * LDT2 + kb) * 2);
                const int n2 = np * 2;
#pragma unroll
                for (int mi = 0; mi < 4; mi++) {
                    mma_h(d[mi][n2],     ah[mi], bh[0], bh[1]);
                    mma_h(d[mi][n2 + 1], ah[mi], bh[2], bh[3]);
                    mma_h(d[mi][n2],     al[mi], bh[0], bh[1]);
                    mma_h(d[mi][n2 + 1], al[mi], bh[2], bh[3]);
                }
            }
        }
        __syncthreads();
    }

    const int bidx  = m0 / SEQ;
    const int cbase = n0 + wn * 64;
    const int cq    = 2 * (lane & 3);
#pragma unroll
    for (int mi = 0; mi < 4; mi++) {
        const int srow0 = (m0 - bidx * SEQ) + wm * 64 + mi * 16 + (lane >> 2);
#pragma unroll
        for (int nt = 0; nt < 8; nt++) {
            const float2 bb = *(const float2*)(bias + cbase + nt * 8 + cq);
            float2 v0 = make_float2(d[mi][nt][0] + bb.x, d[mi][nt][1] + bb.y);
            float2 v1 = make_float2(d[mi][nt][2] + bb.x, d[mi][nt][3] + bb.y);
            if (SCATTER) {
                const int h   = cbase >> 6;
                const int dof = nt * 8 + cq;
                const size_t base = ((size_t)bidx * NH + h) * SEQ;
                uint32_t hi, lo;
                split2(v0, hi, lo);
                *(uint32_t*)&Ch[(base + srow0) * HD + dof] = hi;
                if (Cl) *(uint32_t*)&Cl[(base + srow0) * HD + dof] = lo;
                split2(v1, hi, lo);
                *(uint32_t*)&Ch[(base + srow0 + 8) * HD + dof] = hi;
                if (Cl) *(uint32_t*)&Cl[(base + srow0 + 8) * HD + dof] = lo;
            } else {
                const size_t mrow = (size_t)(m0 + wm * 64 + mi * 16 + (lane >> 2));
                *(float2*)&C[mrow       * DIM + cbase + nt * 8 + cq] = v0;
                *(float2*)&C[(mrow + 8) * DIM + cbase + nt * 8 + cq] = v1;
            }
        }
    }
}

__global__ __launch_bounds__(256, 1)
void qkv_mma_kernel(const hlf* __restrict__ xh, const hlf* __restrict__ xl,
                    const hlf* __restrict__ wh,
                    const float* __restrict__ bq, const float* __restrict__ bk,
                    const float* __restrict__ bv)
{
    const int z = blockIdx.z;
    const hlf* Wh = wh + (size_t)z * DIM * DIM;
    const float* bias = (z == 0) ? bq : (z == 1) ? bk : bv;
    hlf* Ch = (z == 0) ? g_qh : (z == 1) ? g_kh : g_vh;
    hlf* Cl = (z == 0) ? g_ql : nullptr;   // lo needed only for Q (A-side of QK)
    gemm_mma_body<1>(xh, xl, Wh, bias, nullptr, Ch, Cl);
}

__global__ __launch_bounds__(256, 1)
void out_mma_kernel(const hlf* __restrict__ ah, const hlf* __restrict__ al,
                    const hlf* __restrict__ wh,
                    const float* __restrict__ bias, float* __restrict__ C)
{
    gemm_mma_body<0>(ah, al, wh + (size_t)3 * DIM * DIM, bias, C, nullptr, nullptr);
}

// ---------------------------------------------------------------------------
// Register-resident FA2 attention, 2-term fp16:
//   S = (Qh+Ql)·Kh   O += (Ph+Pl)·Vh
// ---------------------------------------------------------------------------
#define ALDT 72
#define ATILE (64 * ALDT)
#define SMEM_ATTN (4 * ATILE * 2)      // Qh Ql Kh Vh = 36864 B

__global__ __launch_bounds__(128)
void attn_mma_kernel(const float* __restrict__ rel_emb)
{
    extern __shared__ __align__(16) char smem[];
    hlf* sQh = (hlf*)smem;
    hlf* sQl = sQh + ATILE;
    hlf* sKh = sQl + ATILE;
    hlf* sVh = sKh + ATILE;

    const int tid  = threadIdx.x;
    const int lane = tid & 31;
    const int w    = tid >> 5;
    const int qt = blockIdx.x, h = blockIdx.y, b = blockIdx.z;
    const size_t bhb = ((size_t)b * NH + h) * SEQ;

    const uint32_t uQh = smem_u32(sQh), uQl = smem_u32(sQl);
    const uint32_t uKh = smem_u32(sKh), uVh = smem_u32(sVh);

    // Q tile hi/lo (synchronous)
    {
        const hlf* Qhp = g_qh + (bhb + qt * 64) * HD;
        const hlf* Qlp = g_ql + (bhb + qt * 64) * HD;
#pragma unroll
        for (int i = 0; i < 4; i++) {
            const int f = tid + i * 128, r = f >> 3, s = (f & 7) * 8;
            *(uint4*)(sQh + r * ALDT + s) = *(const uint4*)(Qhp + r * HD + s);
            *(uint4*)(sQl + r * ALDT + s) = *(const uint4*)(Qlp + r * HD + s);
        }
    }

    // preload K(0)
    {
        const hlf* Khp = g_kh + bhb * HD;
#pragma unroll
        for (int i = 0; i < 4; i++) {
            const int f = tid + i * 128, r = f >> 3, s = (f & 7) * 8;
            cpa16(uKh + (r * ALDT + s) * 2, Khp + r * HD + s);
        }
        CPA_COMMIT();
    }
    __syncthreads();   // Q visible

    const int aRow = w * 16 + (lane & 15);
    const int aK   = ((lane >> 4) & 1) * 8;
    uint32_t qh[4][4], ql[4][4];
#pragma unroll
    for (int ks = 0; ks < 4; ks++) {
        ldsm4(qh[ks], uQh + (aRow * ALDT + ks * 16 + aK) * 2);
        ldsm4(ql[ks], uQl + (aRow * ALDT + ks * 16 + aK) * 2);
    }

    const int bRowL = (lane & 7) + ((lane >> 4) & 1) * 8;
    const int bKoff = ((lane >> 3) & 1) * 8;
    const int vRowL = (lane & 7) + ((lane >> 3) & 1) * 8;
    const int vColL = ((lane >> 4) & 1) * 8;

    const int r0  = lane >> 2;
    const int qiA = qt * 64 + w * 16 + r0;
    const int cq  = 2 * (lane & 3);

    float o[8][4];
#pragma unroll
    for (int nt = 0; nt < 8; nt++)
#pragma unroll
        for (int t = 0; t < 4; t++) o[nt][t] = 0.0f;

    float mA = -1e30f, mB = -1e30f, lA = 0.0f, lB = 0.0f;

    const float bclo = __ldg(rel_emb + 0 * NH + h);
    const float bchi = __ldg(rel_emb + 2 * MAXD * NH + h);

    const int NT = SEQ / 64;
    for (int kt = 0; kt < NT; kt++) {
        // issue V(kt)
        {
            const hlf* Vhp = g_vh + (bhb + kt * 64) * HD;
#pragma unroll
            for (int i = 0; i < 4; i++) {
                const int f = tid + i * 128, r = f >> 3, s = (f & 7) * 8;
                cpa16(uVh + (r * ALDT + s) * 2, Vhp + r * HD + s);
            }
            CPA_COMMIT();
        }
        CPA_WAIT(1);          // K(kt) complete
        __syncthreads();

        // ---- QK^T (2 terms) ----
        float sf[8][4];
#pragma unroll
        for (int nt = 0; nt < 8; nt++)
#pragma unroll
            for (int t = 0; t < 4; t++) sf[nt][t] = 0.0f;

#pragma unroll
        for (int ks = 0; ks < 4; ks++) {
            const int kb = ks * 16 + bKoff;
#pragma unroll
            for (int p = 0; p < 4; p++) {
                uint32_t kh[4];
                ldsm4(kh, uKh + ((p * 16 + bRowL) * ALDT + kb) * 2);
                const int nt = p * 2;
                mma_h(sf[nt],     qh[ks], kh[0], kh[1]);
                mma_h(sf[nt + 1], qh[ks], kh[2], kh[3]);
                mma_h(sf[nt],     ql[ks], kh[0], kh[1]);
                mma_h(sf[nt + 1], ql[ks], kh[2], kh[3]);
            }
        }

        // ---- bias + online softmax ----
        {
            const int dq = qt - kt;
            if (dq >= 3 || dq <= -3) {
                const float bc = (dq >= 3) ? bchi : bclo;
#pragma unroll
                for (int nt = 0; nt < 8; nt++)
#pragma unroll
                    for (int t = 0; t < 4; t++) sf[nt][t] = sf[nt][t] * 0.125f + bc;
            } else {
                const int colb = kt * 64 + cq;
#pragma unroll
                for (int nt = 0; nt < 8; nt++) {
#pragma unroll
                    for (int j = 0; j < 2; j++) {
                        const int col = colb + nt * 8 + j;
                        int dA = qiA - col;
                        dA = max(-MAXD, min(MAXD, dA));
                        int dB = qiA + 8 - col;
                        dB = max(-MAXD, min(MAXD, dB));
                        sf[nt][j]     = sf[nt][j]     * 0.125f + __ldg(rel_emb + (dA + MAXD) * NH + h);
                        sf[nt][2 + j] = sf[nt][2 + j] * 0.125f + __ldg(rel_emb + (dB + MAXD) * NH + h);
                    }
                }
            }

            float mxA = -1e30f, mxB = -1e30f;
#pragma unroll
            for (int nt = 0; nt < 8; nt++) {
                mxA = fmaxf(mxA, fmaxf(sf[nt][0], sf[nt][1]));
                mxB = fmaxf(mxB, fmaxf(sf[nt][2], sf[nt][3]));
            }
            mxA = fmaxf(mxA, __shfl_xor_sync(0xFFFFFFFFu, mxA, 1));
            mxA = fmaxf(mxA, __shfl_xor_sync(0xFFFFFFFFu, mxA, 2));
            mxB = fmaxf(mxB, __shfl_xor_sync(0xFFFFFFFFu, mxB, 1));
            mxB = fmaxf(mxB, __shfl_xor_sync(0xFFFFFFFFu, mxB, 2));

            const float mnA = fmaxf(mA, mxA);
            const float mnB = fmaxf(mB, mxB);
            const float facA = __expf(mA - mnA);
            const float facB = __expf(mB - mnB);
            mA = mnA; mB = mnB;

            float sumA = 0.0f, sumB = 0.0f;
#pragma unroll
            for (int nt = 0; nt < 8; nt++) {
                sf[nt][0] = __expf(sf[nt][0] - mnA);
                sf[nt][1] = __expf(sf[nt][1] - mnA);
                sf[nt][2] = __expf(sf[nt][2] - mnB);
                sf[nt][3] = __expf(sf[nt][3] - mnB);
                sumA += sf[nt][0] + sf[nt][1];
                sumB += sf[nt][2] + sf[nt][3];
            }
            sumA += __shfl_xor_sync(0xFFFFFFFFu, sumA, 1);
            sumA += __shfl_xor_sync(0xFFFFFFFFu, sumA, 2);
            sumB += __shfl_xor_sync(0xFFFFFFFFu, sumB, 1);
            sumB += __shfl_xor_sync(0xFFFFFFFFu, sumB, 2);
            lA = lA * facA + sumA;
            lB = lB * facB + sumB;

#pragma unroll
            for (int nt = 0; nt < 8; nt++) {
                o[nt][0] *= facA; o[nt][1] *= facA;
                o[nt][2] *= facB; o[nt][3] *= facB;
            }
        }

        // ---- P fragments from S C-fragments (exact fp16 split) ----
        uint32_t ph[4][4], pl[4][4];
#pragma unroll
        for (int t = 0; t < 4; t++) {
            split2(make_float2(sf[2 * t][0],     sf[2 * t][1]),     ph[t][0], pl[t][0]);
            split2(make_float2(sf[2 * t][2],     sf[2 * t][3]),     ph[t][1], pl[t][1]);
            split2(make_float2(sf[2 * t + 1][0], sf[2 * t + 1][1]), ph[t][2], pl[t][2]);
            split2(make_float2(sf[2 * t + 1][2], sf[2 * t + 1][3]), ph[t][3], pl[t][3]);
        }

        CPA_WAIT(0);          // V(kt) complete
        __syncthreads();      // V visible; all warps done with K

        // issue K(kt+1)
        if (kt + 1 < NT) {
            const hlf* Khp = g_kh + (bhb + (kt + 1) * 64) * HD;
#pragma unroll
            for (int i = 0; i < 4; i++) {
                const int f = tid + i * 128, r = f >> 3, s = (f & 7) * 8;
                cpa16(uKh + (r * ALDT + s) * 2, Khp + r * HD + s);
            }
            CPA_COMMIT();
        }

        // ---- P @ V (2 terms) ----
#pragma unroll
        for (int t = 0; t < 4; t++) {
            const int kr = t * 16 + vRowL;
#pragma unroll
            for (int nd = 0; nd < 4; nd++) {
                uint32_t vh[4];
                ldsm4t(vh, uVh + (kr * ALDT + nd * 16 + vColL) * 2);
                const int ntd = nd * 2;
                mma_h(o[ntd],     ph[t], vh[0], vh[1]);
                mma_h(o[ntd + 1], ph[t], vh[2], vh[3]);
                mma_h(o[ntd],     pl[t], vh[0], vh[1]);
                mma_h(o[ntd + 1], pl[t], vh[2], vh[3]);
            }
        }
        __syncthreads();      // PV reads done before next V issue
    }

    // ---- epilogue: normalize, split, write [B,S,H*Hd] as fp16 hi/lo ----
    {
        const float iA = 1.0f / lA, iB = 1.0f / lB;
        const int rowA = qt * 64 + w * 16 + r0;
#pragma unroll
        for (int nt = 0; nt < 8; nt++) {
            const int col = h * HD + nt * 8 + cq;
            const size_t a0 = ((size_t)b * SEQ + rowA)     * DIM + col;
            const size_t a1 = ((size_t)b * SEQ + rowA + 8) * DIM + col;
            uint32_t hi, lo;
            split2(make_float2(o[nt][0] * iA, o[nt][1] * iA), hi, lo);
            *(uint32_t*)(g_ath + a0) = hi;
            *(uint32_t*)(g_atl + a0) = lo;
            split2(make_float2(o[nt][2] * iB, o[nt][3] * iB), hi, lo);
            *(uint32_t*)(g_ath + a1) = hi;
            *(uint32_t*)(g_atl + a1) = lo;
        }
    }
}

// ---------------------------------------------------------------------------
extern "C" void kernel_launch(void* const* d_in, const int* in_sizes, int n_in,
                              void* d_out, int out_size)
{
    const float* x   = (const float*)d_in[0];
    const float* Wq  = (const float*)d_in[1];
    const float* bq  = (const float*)d_in[2];
    const float* Wk  = (const float*)d_in[3];
    const float* bk  = (const float*)d_in[4];
    const float* Wv  = (const float*)d_in[5];
    const float* bv  = (const float*)d_in[6];
    const float* Wo  = (const float*)d_in[7];
    const float* bo  = (const float*)d_in[8];
    const float* rel = (const float*)d_in[9];
    float* out = (float*)d_out;

    hlf *xh, *xl, *wh, *ath, *atl;
    cudaGetSymbolAddress((void**)&xh,  g_xh);
    cudaGetSymbolAddress((void**)&xl,  g_xl);
    cudaGetSymbolAddress((void**)&wh,  g_wh);
    cudaGetSymbolAddress((void**)&ath, g_ath);
    cudaGetSymbolAddress((void**)&atl, g_atl);

    split_all_kernel<<<4096 + 4 * 1024, 256>>>(x, Wq, Wk, Wv, Wo);

    cudaFuncSetAttribute(qkv_mma_kernel, cudaFuncAttributeMaxDynamicSharedMemorySize, SMEM_GEMM);
    cudaFuncSetAttribute(out_mma_kernel, cudaFuncAttributeMaxDynamicSharedMemorySize, SMEM_GEMM);
    cudaFuncSetAttribute(attn_mma_kernel, cudaFuncAttributeMaxDynamicSharedMemorySize, SMEM_ATTN);

    dim3 gq(DIM / BN, MTOT / BM, 3);
    qkv_mma_kernel<<<gq, 256, SMEM_GEMM>>>(xh, xl, wh, bq, bk, bv);

    dim3 ga(SEQ / 64, NH, BATCH);
    attn_mma_kernel<<<ga, 128, SMEM_ATTN>>>(rel);

    dim3 go(DIM / BN, MTOT / BM);
    out_mma_kernel<<<go, 256, SMEM_GEMM>>>(ath, atl, wh, bo, out);
}